// round 4
// baseline (speedup 1.0000x reference)
#include <cuda_runtime.h>
#include <cstdint>

#define N 256
#define NP 65536u
#define NVOX 16777216u

// Packed xy-box intermediates: float4{sum_i,sum_r,sum_ii,sum_rr} + float{sum_ir}
__device__ float4 g_sum4[16777216];
__device__ float  g_sum1[16777216];

// ===========================================================================
// Kernel 1: 5x5 box in X (warp shuffles) and Y (per-thread register ring).
// No shared memory, no barriers. Warp spans 32 consecutive x; CTA of 8 warps
// covers the full x row at one z; marches a 64-row y chunk (+4 halo rows).
// ===========================================================================
#define K1_YC 64

__global__ __launch_bounds__(256) void boxxy_kernel(
    const float* __restrict__ img, const float* __restrict__ ref)
{
    const unsigned FULL = 0xFFFFFFFFu;
    const int lane = threadIdx.x & 31;
    const int warp = threadIdx.x >> 5;
    const int x = (warp << 5) + lane;          // 0..255
    const int z = blockIdx.x;                  // 0..255
    const int y0 = blockIdx.y * K1_YC;
    const unsigned zoff = (unsigned)z * NP;

    // 5-deep y rings of the 5 x-boxed quantities
    float qi[5], qr[5], qii[5], qrr[5], qir[5];
#pragma unroll
    for (int k = 0; k < 5; k++) qi[k] = qr[k] = qii[k] = qrr[k] = qir[k] = 0.f;

    for (int t = 0; t < K1_YC + 4; ++t) {
        const int yy = y0 - 2 + t;
        const bool in = (yy >= 0) & (yy < N);
        const unsigned rb = zoff + (unsigned)(in ? yy : 0) * N;

        float vi = in ? __ldg(img + rb + x) : 0.f;
        float vr = in ? __ldg(ref + rb + x) : 0.f;

        float vim1 = __shfl_up_sync(FULL, vi, 1);
        float vim2 = __shfl_up_sync(FULL, vi, 2);
        float vip1 = __shfl_down_sync(FULL, vi, 1);
        float vip2 = __shfl_down_sync(FULL, vi, 2);
        float rim1 = __shfl_up_sync(FULL, vr, 1);
        float rim2 = __shfl_up_sync(FULL, vr, 2);
        float rip1 = __shfl_down_sync(FULL, vr, 1);
        float rip2 = __shfl_down_sync(FULL, vr, 2);

        // patch warp-edge lanes with direct (L1-resident) loads, zero-padded
        if (lane < 2) {
            vim2 = (in && x >= 2) ? __ldg(img + rb + x - 2) : 0.f;
            rim2 = (in && x >= 2) ? __ldg(ref + rb + x - 2) : 0.f;
            if (lane == 0) {
                vim1 = (in && x >= 1) ? __ldg(img + rb + x - 1) : 0.f;
                rim1 = (in && x >= 1) ? __ldg(ref + rb + x - 1) : 0.f;
            }
        }
        if (lane >= 30) {
            vip2 = (in && x + 2 < N) ? __ldg(img + rb + x + 2) : 0.f;
            rip2 = (in && x + 2 < N) ? __ldg(ref + rb + x + 2) : 0.f;
            if (lane == 31) {
                vip1 = (in && x + 1 < N) ? __ldg(img + rb + x + 1) : 0.f;
                rip1 = (in && x + 1 < N) ? __ldg(ref + rb + x + 1) : 0.f;
            }
        }

        // x-boxed quantities for this row
        const float s_i  = vim2 + vim1 + vi + vip1 + vip2;
        const float s_r  = rim2 + rim1 + vr + rip1 + rip2;
        const float s_ii = vim2*vim2 + vim1*vim1 + vi*vi + vip1*vip1 + vip2*vip2;
        const float s_rr = rim2*rim2 + rim1*rim1 + vr*vr + rip1*rip1 + rip2*rip2;
        const float s_ir = vim2*rim2 + vim1*rim1 + vi*vr + vip1*rip1 + vip2*rip2;

        // shift rings, push
#pragma unroll
        for (int k = 0; k < 4; k++) {
            qi[k] = qi[k+1]; qr[k] = qr[k+1]; qii[k] = qii[k+1];
            qrr[k] = qrr[k+1]; qir[k] = qir[k+1];
        }
        qi[4] = s_i; qr[4] = s_r; qii[4] = s_ii; qrr[4] = s_rr; qir[4] = s_ir;

        // output row y = yy - 2
        if (t >= 4) {
            const unsigned o = zoff + (unsigned)(yy - 2) * N + (unsigned)x;
            float4 v;
            v.x = qi[0] + qi[1] + qi[2] + qi[3] + qi[4];
            v.y = qr[0] + qr[1] + qr[2] + qr[3] + qr[4];
            v.z = qii[0] + qii[1] + qii[2] + qii[3] + qii[4];
            v.w = qrr[0] + qrr[1] + qrr[2] + qrr[3] + qrr[4];
            g_sum4[o] = v;
            g_sum1[o] = qir[0] + qir[1] + qir[2] + qir[3] + qir[4];
        }
    }
}

// ===========================================================================
// Kernel 2: z-box via 5-deep register ring over packed intermediates +
// gradients + force epilogue. Thread per (x,y), marching 32-plane z chunk.
// x±1 gradient neighbors come from warp shuffles of the held center values.
// ===========================================================================
#define K2_ZC 32

__global__ __launch_bounds__(256) void zbox_final_kernel(
    const float* __restrict__ img, const float* __restrict__ ref,
    float* __restrict__ out)
{
    const unsigned FULL = 0xFFFFFFFFu;
    const int x = threadIdx.x;
    const int lane = x & 31;
    const int y = blockIdx.x;
    const int z0 = blockIdx.y * K2_ZC;
    const unsigned base = (unsigned)y * N + (unsigned)x;

    const float npix = 125.0f;
    const float inv_npix = 1.0f / 125.0f;

    float4 r4[5];
    float  r1[5];
    float c_i[3], c_r[3];

    // prologue: slots 1..4 = planes z0-2 .. z0+1
#pragma unroll
    for (int k = 0; k < 4; k++) {
        int zz = z0 - 2 + k;
        bool in = (zz >= 0) & (zz < N);
        unsigned o = (unsigned)(in ? zz : 0) * NP + base;
        float4 v = in ? __ldg(&g_sum4[o]) : make_float4(0.f, 0.f, 0.f, 0.f);
        float  w = in ? __ldg(&g_sum1[o]) : 0.f;
        r4[k + 1] = v;
        r1[k + 1] = w;
    }
    {
        bool inm = (z0 - 1) >= 0;
        unsigned om = (unsigned)(inm ? (z0 - 1) : 0) * NP + base;
        c_i[1] = inm ? __ldg(img + om) : 0.f;
        c_r[1] = inm ? __ldg(ref + om) : 0.f;
        unsigned oc = (unsigned)z0 * NP + base;
        c_i[2] = __ldg(img + oc);
        c_r[2] = __ldg(ref + oc);
    }

    for (int z = z0; z < z0 + K2_ZC; ++z) {
        // shift rings
#pragma unroll
        for (int k = 0; k < 4; k++) { r4[k] = r4[k+1]; r1[k] = r1[k+1]; }
        c_i[0] = c_i[1]; c_i[1] = c_i[2];
        c_r[0] = c_r[1]; c_r[1] = c_r[2];

        // push plane z+2 (sums) and z+1 (centers)
        {
            int zz = z + 2;
            bool in = zz < N;
            unsigned o = (unsigned)(in ? zz : 0) * NP + base;
            r4[4] = in ? __ldg(&g_sum4[o]) : make_float4(0.f, 0.f, 0.f, 0.f);
            r1[4] = in ? __ldg(&g_sum1[o]) : 0.f;
            int zc = z + 1;
            bool inc = zc < N;
            unsigned oc = (unsigned)(inc ? zc : 0) * NP + base;
            c_i[2] = inc ? __ldg(img + oc) : 0.f;
            c_r[2] = inc ? __ldg(ref + oc) : 0.f;
        }

        const unsigned idx = (unsigned)z * NP + base;
        const float ci = c_i[1], cr = c_r[1];

        // x±1 neighbors via shuffle of the held centers; warp-edge lanes load
        float xi_p = __shfl_down_sync(FULL, ci, 1);
        float xr_p = __shfl_down_sync(FULL, cr, 1);
        float xi_m = __shfl_up_sync(FULL, ci, 1);
        float xr_m = __shfl_up_sync(FULL, cr, 1);
        if (lane == 31 && x < N - 1) {
            xi_p = __ldg(img + idx + 1);
            xr_p = __ldg(ref + idx + 1);
        }
        if (lane == 0 && x > 0) {
            xi_m = __ldg(img + idx - 1);
            xr_m = __ldg(ref + idx - 1);
        }

        // y±1 neighbors
        float yi_p = (y < N - 1) ? __ldg(img + idx + N) : 0.f;
        float yi_m = (y > 0)     ? __ldg(img + idx - N) : 0.f;
        float yr_p = (y < N - 1) ? __ldg(ref + idx + N) : 0.f;
        float yr_m = (y > 0)     ? __ldg(ref + idx - N) : 0.f;

        // z-box sums
        const float sum_i  = r4[0].x + r4[1].x + r4[2].x + r4[3].x + r4[4].x;
        const float sum_r  = r4[0].y + r4[1].y + r4[2].y + r4[3].y + r4[4].y;
        const float sum_ii = r4[0].z + r4[1].z + r4[2].z + r4[3].z + r4[4].z;
        const float sum_rr = r4[0].w + r4[1].w + r4[2].w + r4[3].w + r4[4].w;
        const float sum_ir = r1[0] + r1[1] + r1[2] + r1[3] + r1[4];

        // faithful to reference: reference mean uses sum_i
        const float mi = sum_i * inv_npix;
        const float mr = mi;

        const float var_r = sum_rr - 2.0f * mr * sum_r + npix * mr * mr;
        const float var_i = sum_ii - 2.0f * mi * sum_i + npix * mi * mi;
        const float cross = sum_ir - mr * sum_i - mi * sum_r + npix * mi * mr;

        // gradients: central inside, one-sided at edges
        float gxi, gxr, gyi, gyr, gzi, gzr;
        if (x == 0)          { gxi = xi_p - ci; gxr = xr_p - cr; }
        else if (x == N - 1) { gxi = ci - xi_m; gxr = cr - xr_m; }
        else { gxi = 0.5f * (xi_p - xi_m); gxr = 0.5f * (xr_p - xr_m); }

        if (y == 0)          { gyi = yi_p - ci; gyr = yr_p - cr; }
        else if (y == N - 1) { gyi = ci - yi_m; gyr = cr - yr_m; }
        else { gyi = 0.5f * (yi_p - yi_m); gyr = 0.5f * (yr_p - yr_m); }

        if (z == 0)          { gzi = c_i[2] - ci; gzr = c_r[2] - cr; }
        else if (z == N - 1) { gzi = ci - c_i[0]; gzr = cr - c_r[0]; }
        else { gzi = 0.5f * (c_i[2] - c_i[0]); gzr = 0.5f * (c_r[2] - c_r[0]); }

        const float gd = 0.5f * (gzi + gzr);
        const float gh = 0.5f * (gyi + gyr);
        const float gw = 0.5f * (gxi + gxr);

        const float factor =
            2.0f * cross / (var_i * var_r + 1e-6f) * (ci - cross / var_r * cr);

        out[idx]             = -factor * gd;
        out[NVOX + idx]      = -factor * gh;
        out[2u * NVOX + idx] = -factor * gw;
    }
}

// ---------------------------------------------------------------------------
extern "C" void kernel_launch(void* const* d_in, const int* in_sizes, int n_in,
                              void* d_out, int out_size)
{
    const float* img = (const float*)d_in[0];   // image
    const float* ref = (const float*)d_in[2];   // reference_image
    float* out = (float*)d_out;

    {
        dim3 block(256, 1, 1);
        dim3 grid(N, N / K1_YC, 1);
        boxxy_kernel<<<grid, block>>>(img, ref);
    }
    {
        dim3 block(256, 1, 1);
        dim3 grid(N, N / K2_ZC, 1);
        zbox_final_kernel<<<grid, block>>>(img, ref, out);
    }
}